// round 5
// baseline (speedup 1.0000x reference)
#include <cuda_runtime.h>
#include <cstdint>
#include <math_constants.h>

#define NHEADS 32
#define HD     128
#define NB     2
#define NS     2048
#define NH     4096
#define NTOK   (NB*NS)   // 4096 tokens

// ---------------- scratch (device globals: no allocations allowed) ----------
__device__ float g_q[(size_t)NB*NHEADS*NS*HD];    // [b][h][s][d]
__device__ float g_k[(size_t)NB*NHEADS*NS*HD];
__device__ float g_v[(size_t)NB*NHEADS*NS*HD];
__device__ float g_ctx[(size_t)NTOK*NH];          // token-major [b*s][h*d]

// ---------------- helpers ----------------------------------------------------
__device__ __forceinline__ float tf32f(float x) {
    unsigned u; asm("cvt.rna.tf32.f32 %0, %1;" : "=r"(u) : "f"(x));
    return __uint_as_float(u);
}

__device__ __forceinline__ void mma8(float* d, const unsigned* a, const unsigned* b) {
    asm volatile(
        "mma.sync.aligned.m16n8k8.row.col.f32.tf32.tf32.f32 "
        "{%0,%1,%2,%3}, {%4,%5,%6,%7}, {%8,%9}, {%0,%1,%2,%3};\n"
        : "+f"(d[0]), "+f"(d[1]), "+f"(d[2]), "+f"(d[3])
        : "r"(a[0]), "r"(a[1]), "r"(a[2]), "r"(a[3]), "r"(b[0]), "r"(b[1]));
}

__device__ __forceinline__ void scatter_qkv(int m, int n, float v) {
    int b = m >> 11, s = m & 2047;
    int which = n >> 12, rem = n & 4095;
    int h = rem >> 7, d = rem & 127;
    size_t idx = ((((size_t)b * NHEADS + h) * NS) + s) * HD + d;
    float* dst = (which == 0) ? g_q : (which == 1) ? g_k : g_v;
    dst[idx] = v;
}

// =============================================================================
// GEMM: C[M,N] = A[M,K] @ W[K,N] + bias.  CTA 128x128, ktile 32, 256 thr.
// Shared memory holds tiles in *mma fragment order* with per-block XOR swizzle:
//   A-operand: blocks [mt][kstep] of 128 floats = [lane^c][j0..j3] -> LDS.128
//   B-operand: blocks [nt][kstep] of  64 floats = [lane^c][j0..j1] -> LDS.64
// Double-buffered smem + register prefetch: 1 syncthreads per ktile.
// =============================================================================
template<int MODE>
__global__ __launch_bounds__(256, 2) void gemm_tf32(
    const float* __restrict__ A, const float* __restrict__ W,
    const float* __restrict__ bias, float* __restrict__ C,
    int M, int N, int K)
{
    extern __shared__ float dsm[];   // [A0 4096 | B0 4096 | A1 4096 | B1 4096]

    const int tid  = threadIdx.x;
    const int warp = tid >> 5, lane = tid & 31;
    const int wm = warp >> 1, wn = warp & 1;
    const int lq = lane & 3, lr = lane >> 2;
    const int brow = blockIdx.y * 128, bcol = blockIdx.x * 128;

    const float* Aptr = (MODE == 1) ? (const float*)g_ctx : A;
    const float* gA = Aptr + (size_t)brow * K;
    const float* gB = W + bcol;

    // ---- store-side constants (A tile: row=tid>>3 (+32i), c4=(tid&7)*4) ----
    const int aRow0 = tid >> 3;               // 0..31
    const int aC4   = (tid & 7) << 2;         // 0..28
    const int aLr4  = (aRow0 & 7) << 2;
    const int aJ    = ((aRow0 >> 3) & 1) + (((aC4 >> 2) & 1) << 1);
    const int aKs   = aC4 >> 3;
    const int aMt0  = aRow0 >> 4;
    // ---- store-side constants (B tile: k=tid>>5 (+8i), c4=(tid&31)*4) -------
    const int bNt   = (tid & 31) >> 1;
    const int bLr   = (tid & 1) << 2;
    const int bK    = tid >> 5;               // 0..7
    const int bLq   = bK & 3;
    const int bJ    = bK >> 2;
    const int bC4   = (tid & 31) << 2;

    float acc[2][8][4];
    #pragma unroll
    for (int mi = 0; mi < 2; mi++)
        #pragma unroll
        for (int ni = 0; ni < 8; ni++)
            #pragma unroll
            for (int j = 0; j < 4; j++) acc[mi][ni][j] = 0.f;

    float4 pa[4], pb[4];

    // prologue: load tile 0
    #pragma unroll
    for (int i = 0; i < 4; i++)
        pa[i] = *(const float4*)(gA + (size_t)(aRow0 + 32*i) * K + aC4);
    #pragma unroll
    for (int i = 0; i < 4; i++)
        pb[i] = *(const float4*)(gB + (size_t)(bK + 8*i) * N + bC4);

    // store tile 0 -> buffer 0 (with tf32 rounding)
    {
        float* Ab = dsm;  float* Bb = dsm + 4096;
        #pragma unroll
        for (int i = 0; i < 4; i++) {
            int blk = (aMt0 + 2*i)*4 + aKs;  int c = blk & 31;
            float* d = Ab + blk*128 + aJ;
            d[((aLr4+0)^c)<<2] = tf32f(pa[i].x);
            d[((aLr4+1)^c)<<2] = tf32f(pa[i].y);
            d[((aLr4+2)^c)<<2] = tf32f(pa[i].z);
            d[((aLr4+3)^c)<<2] = tf32f(pa[i].w);
        }
        #pragma unroll
        for (int i = 0; i < 4; i++) {
            int blk = bNt*4 + i;  int c = (blk>>2) ^ (blk&3);
            float* d = Bb + blk*64 + bJ;
            d[((((bLr+0)<<2)+bLq)^c)<<1] = tf32f(pb[i].x);
            d[((((bLr+1)<<2)+bLq)^c)<<1] = tf32f(pb[i].y);
            d[((((bLr+2)<<2)+bLq)^c)<<1] = tf32f(pb[i].z);
            d[((((bLr+3)<<2)+bLq)^c)<<1] = tf32f(pb[i].w);
        }
    }
    __syncthreads();

    const int ntiles = K >> 5;
    for (int kt = 0; kt < ntiles; kt++) {
        const bool nxt = (kt + 1 < ntiles);
        if (nxt) {
            const float* gA2 = gA + (kt+1)*32;
            #pragma unroll
            for (int i = 0; i < 4; i++)
                pa[i] = *(const float4*)(gA2 + (size_t)(aRow0 + 32*i) * K + aC4);
            const float* gB2 = gB + (size_t)(kt+1)*32 * N;
            #pragma unroll
            for (int i = 0; i < 4; i++)
                pb[i] = *(const float4*)(gB2 + (size_t)(bK + 8*i) * N + bC4);
        }

        const float4* As4 = (const float4*)(dsm + (kt & 1) * 8192);
        const float2* Bs2 = (const float2*)(dsm + (kt & 1) * 8192 + 4096);
        #pragma unroll
        for (int ks = 0; ks < 4; ks++) {
            float4 af0, af1;
            { int blk = (wm*2+0)*4 + ks; af0 = As4[blk*32 + (lane ^ (blk & 31))]; }
            { int blk = (wm*2+1)*4 + ks; af1 = As4[blk*32 + (lane ^ (blk & 31))]; }
            #pragma unroll
            for (int ni = 0; ni < 8; ni++) {
                int blk = (wn*8+ni)*4 + ks;
                int c = (blk>>2) ^ (blk&3);
                float2 bf = Bs2[blk*32 + (lane ^ c)];
                mma8(acc[0][ni], (const unsigned*)&af0, (const unsigned*)&bf);
                mma8(acc[1][ni], (const unsigned*)&af1, (const unsigned*)&bf);
            }
        }

        if (nxt) {
            float* Ab = dsm + ((kt+1) & 1) * 8192;
            float* Bb = Ab + 4096;
            #pragma unroll
            for (int i = 0; i < 4; i++) {
                int blk = (aMt0 + 2*i)*4 + aKs;  int c = blk & 31;
                float* d = Ab + blk*128 + aJ;
                d[((aLr4+0)^c)<<2] = tf32f(pa[i].x);
                d[((aLr4+1)^c)<<2] = tf32f(pa[i].y);
                d[((aLr4+2)^c)<<2] = tf32f(pa[i].z);
                d[((aLr4+3)^c)<<2] = tf32f(pa[i].w);
            }
            #pragma unroll
            for (int i = 0; i < 4; i++) {
                int blk = bNt*4 + i;  int c = (blk>>2) ^ (blk&3);
                float* d = Bb + blk*64 + bJ;
                d[((((bLr+0)<<2)+bLq)^c)<<1] = tf32f(pb[i].x);
                d[((((bLr+1)<<2)+bLq)^c)<<1] = tf32f(pb[i].y);
                d[((((bLr+2)<<2)+bLq)^c)<<1] = tf32f(pb[i].z);
                d[((((bLr+3)<<2)+bLq)^c)<<1] = tf32f(pb[i].w);
            }
        }
        __syncthreads();
    }

    // epilogue
    #pragma unroll
    for (int mi = 0; mi < 2; mi++) {
        int r0 = brow + wm * 32 + mi * 16 + lr;
        #pragma unroll
        for (int ni = 0; ni < 8; ni++) {
            int c0 = bcol + wn * 64 + ni * 8 + 2 * lq;
            float v0 = acc[mi][ni][0] + bias[c0];
            float v1 = acc[mi][ni][1] + bias[c0 + 1];
            float v2 = acc[mi][ni][2] + bias[c0];
            float v3 = acc[mi][ni][3] + bias[c0 + 1];
            if (MODE == 0) {
                scatter_qkv(r0,     c0,     v0);
                scatter_qkv(r0,     c0 + 1, v1);
                scatter_qkv(r0 + 8, c0,     v2);
                scatter_qkv(r0 + 8, c0 + 1, v3);
            } else {
                C[(size_t)r0 * N + c0]           = v0;
                C[(size_t)r0 * N + c0 + 1]       = v1;
                C[(size_t)(r0 + 8) * N + c0]     = v2;
                C[(size_t)(r0 + 8) * N + c0 + 1] = v3;
            }
        }
    }
}

// =============================================================================
// Flash attention: CTA = 128 q-rows x full head, 256 threads = 8 warps
// (warp w owns q rows w*16..w*16+15). KV tile 64. Fragment-order smem:
//   Qs: A-op [mt=8][ks=16] blocks of 128  (64KB)
//   Ks: B-op [nt=8][ks=16] blocks of 64   (32KB)
//   Vs: B-op [nt=16][ks=8] blocks of 64   (32KB)
//   Ps: A-op [mt=8][ks=8]  blocks of 128  (32KB, no swizzle, warp-private)
// =============================================================================
#define FL_QS  0
#define FL_KS  16384
#define FL_VS  24576
#define FL_PS  32768
#define SMEM_FLASH (40960 * 4)   // 160 KB

__global__ __launch_bounds__(256, 1) void flash_attn()
{
    extern __shared__ float sm[];
    float* Qs = sm + FL_QS;
    float* Ks = sm + FL_KS;
    float* Vs = sm + FL_VS;
    float* Ps = sm + FL_PS;

    const int tid = threadIdx.x, w = tid >> 5, lane = tid & 31;
    const int lq = lane & 3, lr = lane >> 2;
    const int bh = blockIdx.y, qt = blockIdx.x;
    const float scale = 0.08838834764831845f;  // 1/sqrt(128)

    const float* Qg = g_q + ((size_t)bh * NS + qt * 128) * HD;
    const float* Kg = g_k + (size_t)bh * NS * HD;
    const float* Vg = g_v + (size_t)bh * NS * HD;

    // ---- load Q tile 128x128 into fragment layout (pre-scaled, tf32) -------
    {
        const int c4  = (tid & 31) << 2;
        const int ksq = c4 >> 3;
        const int jc  = ((c4 >> 2) & 1) << 1;
        #pragma unroll
        for (int i = 0; i < 16; i++) {
            int row = (tid >> 5) + 8 * i;
            float4 v = *(const float4*)(Qg + (size_t)row * HD + c4);
            int rr = row & 15;
            int blk = (row >> 4) * 16 + ksq;
            int c = blk & 31;
            int j = (rr >> 3) + jc;
            int lt = (rr & 7) << 2;
            float* d = Qs + blk * 128 + j;
            d[((lt+0)^c)<<2] = tf32f(v.x * scale);
            d[((lt+1)^c)<<2] = tf32f(v.y * scale);
            d[((lt+2)^c)<<2] = tf32f(v.z * scale);
            d[((lt+3)^c)<<2] = tf32f(v.w * scale);
        }
    }

    float oacc[16][4];
    #pragma unroll
    for (int ni = 0; ni < 16; ni++)
        #pragma unroll
        for (int j = 0; j < 4; j++) oacc[ni][j] = 0.f;

    float m0 = -CUDART_INF_F, m1 = -CUDART_INF_F, l0 = 0.f, l1 = 0.f;

    // K/V store-side constants
    const int c4kv = (tid & 31) << 2;
    const int kwrp = tid >> 5;                 // kv low bits
    const int ksK  = (tid & 31) >> 1;          // d>>3
    const int jK   = tid & 1;
    const int ltK  = kwrp << 2;
    const int ntV  = (tid & 31) >> 1;
    const int lrVb = (tid & 1) << 2;
    const int lqV  = kwrp & 3;
    const int jV   = kwrp >> 2;
    // P store constants
    const int ltP  = (lr << 2) + ((lq & 1) << 1);
    const int jP   = (lq >> 1) << 1;

    for (int kt = 0; kt < NS / 64; kt++) {
        __syncthreads();   // Q ready (1st iter) / prior PV done
        #pragma unroll
        for (int i = 0; i < 8; i++) {
            int kv = kwrp + 8 * i;
            float4 kvec = *(const float4*)(Kg + (size_t)(kt*64 + kv) * HD + c4kv);
            int blkK = i * 16 + ksK;
            int cK = blkK & 15;
            float* dK = Ks + blkK * 64 + jK;
            dK[((ltK+0)^cK)<<1] = tf32f(kvec.x);
            dK[((ltK+1)^cK)<<1] = tf32f(kvec.y);
            dK[((ltK+2)^cK)<<1] = tf32f(kvec.z);
            dK[((ltK+3)^cK)<<1] = tf32f(kvec.w);
            float4 vvec = *(const float4*)(Vg + (size_t)(kt*64 + kv) * HD + c4kv);
            int blkV = ntV * 8 + i;
            int cV = blkV >> 3;
            float* dV = Vs + blkV * 64 + jV;
            dV[((((lrVb+0)<<2)+lqV)^cV)<<1] = tf32f(vvec.x);
            dV[((((lrVb+1)<<2)+lqV)^cV)<<1] = tf32f(vvec.y);
            dV[((((lrVb+2)<<2)+lqV)^cV)<<1] = tf32f(vvec.z);
            dV[((((lrVb+3)<<2)+lqV)^cV)<<1] = tf32f(vvec.w);
        }
        __syncthreads();

        // ---- S = Q K^T : warp = 16 q-rows x 64 kv-cols, k = 128 ------------
        float sacc[8][4];
        #pragma unroll
        for (int ni = 0; ni < 8; ni++)
            #pragma unroll
            for (int j = 0; j < 4; j++) sacc[ni][j] = 0.f;

        #pragma unroll
        for (int ks = 0; ks < 16; ks++) {
            int blkQ = w * 16 + ks;
            float4 qa = ((const float4*)Qs)[blkQ * 32 + (lane ^ (blkQ & 31))];
            #pragma unroll
            for (int ni = 0; ni < 8; ni++) {
                int blkK = ni * 16 + ks;
                float2 kb = ((const float2*)Ks)[blkK * 32 + (lane ^ (blkK & 15))];
                mma8(sacc[ni], (const unsigned*)&qa, (const unsigned*)&kb);
            }
        }

        // ---- online softmax ------------------------------------------------
        float mt0 = -CUDART_INF_F, mt1 = -CUDART_INF_F;
        #pragma unroll
        for (int ni = 0; ni < 8; ni++) {
            mt0 = fmaxf(mt0, fmaxf(sacc[ni][0], sacc[ni][1]));
            mt1 = fmaxf(mt1, fmaxf(sacc[ni][2], sacc[ni][3]));
        }
        mt0 = fmaxf(mt0, __shfl_xor_sync(0xffffffffu, mt0, 1));
        mt0 = fmaxf(mt0, __shfl_xor_sync(0xffffffffu, mt0, 2));
        mt1 = fmaxf(mt1, __shfl_xor_sync(0xffffffffu, mt1, 1));
        mt1 = fmaxf(mt1, __shfl_xor_sync(0xffffffffu, mt1, 2));

        float mn0 = fmaxf(m0, mt0), mn1 = fmaxf(m1, mt1);
        float a0 = __expf(m0 - mn0), a1 = __expf(m1 - mn1);

        float sum0 = 0.f, sum1 = 0.f;
        #pragma unroll
        for (int ni = 0; ni < 8; ni++) {
            float p0 = __expf(sacc[ni][0] - mn0);
            float p1 = __expf(sacc[ni][1] - mn0);
            float p2 = __expf(sacc[ni][2] - mn1);
            float p3 = __expf(sacc[ni][3] - mn1);
            sum0 += p0 + p1;  sum1 += p2 + p3;
            float* d = Ps + (w * 8 + ni) * 128;
            int a = (ltP << 2) + jP;
            d[a]     = tf32f(p0);
            d[a + 1] = tf32f(p2);
            d[a + 4] = tf32f(p1);
            d[a + 5] = tf32f(p3);
        }
        sum0 += __shfl_xor_sync(0xffffffffu, sum0, 1);
        sum0 += __shfl_xor_sync(0xffffffffu, sum0, 2);
        sum1 += __shfl_xor_sync(0xffffffffu, sum1, 1);
        sum1 += __shfl_xor_sync(0xffffffffu, sum1, 2);

        l0 = l0 * a0 + sum0;
        l1 = l1 * a1 + sum1;
        m0 = mn0; m1 = mn1;

        #pragma unroll
        for (int ni = 0; ni < 16; ni++) {
            oacc[ni][0] *= a0; oacc[ni][1] *= a0;
            oacc[ni][2] *= a1; oacc[ni][3] *= a1;
        }
        __syncwarp();  // order warp-private P writes before frag reads

        // ---- O += P V : warp = 16 rows x 128 d-cols, k = 64 ----------------
        #pragma unroll
        for (int ks = 0; ks < 8; ks++) {
            int blkP = w * 8 + ks;
            float4 pa = ((const float4*)Ps)[blkP * 32 + lane];
            #pragma unroll
            for (int nt = 0; nt < 16; nt++) {
                int blkV = nt * 8 + ks;
                float2 vb = ((const float2*)Vs)[blkV * 32 + (lane ^ (blkV >> 3))];
                mma8(oacc[nt], (const unsigned*)&pa, (const unsigned*)&vb);
            }
        }
    }

    // ---- epilogue: normalize, write ctx token-major -------------------------
    float inv0 = 1.f / l0, inv1 = 1.f / l1;
    int b = bh >> 5, h = bh & 31;
    int row0 = qt * 128 + w * 16 + lr;
    size_t tok0 = ((size_t)b * NS + row0) * NH;
    size_t tok1 = ((size_t)b * NS + row0 + 8) * NH;
    #pragma unroll
    for (int nt = 0; nt < 16; nt++) {
        int col = h * HD + nt * 8 + 2 * lq;
        g_ctx[tok0 + col]     = oacc[nt][0] * inv0;
        g_ctx[tok0 + col + 1] = oacc[nt][1] * inv0;
        g_ctx[tok1 + col]     = oacc[nt][2] * inv1;
        g_ctx[tok1 + col + 1] = oacc[nt][3] * inv1;
    }
}

// ---------------- launch ------------------------------------------------------
extern "C" void kernel_launch(void* const* d_in, const int* in_sizes, int n_in,
                              void* d_out, int out_size)
{
    const float* x    = (const float*)d_in[0];
    const float* wqkv = (const float*)d_in[1];
    const float* bqkv = (const float*)d_in[2];
    const float* wo   = (const float*)d_in[3];
    const float* bo   = (const float*)d_in[4];
    float* out = (float*)d_out;

    cudaFuncSetAttribute(gemm_tf32<0>, cudaFuncAttributeMaxDynamicSharedMemorySize, 65536);
    cudaFuncSetAttribute(gemm_tf32<1>, cudaFuncAttributeMaxDynamicSharedMemorySize, 65536);
    cudaFuncSetAttribute(flash_attn,   cudaFuncAttributeMaxDynamicSharedMemorySize, SMEM_FLASH);

    // 1) QKV GEMM + bias, scattered into [b][h][s][d] Q/K/V
    gemm_tf32<0><<<dim3(3 * NH / 128, NTOK / 128), 256, 65536>>>(
        x, wqkv, bqkv, nullptr, NTOK, 3 * NH, NH);

    // 2) flash attention -> ctx (token-major)
    flash_attn<<<dim3(NS / 128, NB * NHEADS), 256, SMEM_FLASH>>>();

    // 3) output projection + bias
    gemm_tf32<1><<<dim3(NH / 128, NTOK / 128), 256, 65536>>>(
        nullptr, wo, bo, out, NTOK, NH, NH);
}

// round 6
// speedup vs baseline: 1.9707x; 1.9707x over previous
#include <cuda_runtime.h>
#include <cstdint>
#include <math_constants.h>

#define NHEADS 32
#define HD     128
#define NB     2
#define NS     2048
#define NH     4096
#define NTOK   (NB*NS)   // 4096 tokens
#define QSCALE 0.08838834764831845f   // 1/sqrt(128)

// ---------------- scratch (device globals: no allocations allowed) ----------
__device__ float g_q[(size_t)NB*NHEADS*NS*HD];    // [b][h][s][d]  (pre-scaled+rounded)
__device__ float g_k[(size_t)NB*NHEADS*NS*HD];    // rounded
__device__ float g_v[(size_t)NB*NHEADS*NS*HD];    // rounded
__device__ float g_ctx[(size_t)NTOK*NH];          // token-major, rounded
__device__ float g_xr[(size_t)NTOK*NH];           // rounded x
__device__ float g_wqkvr[(size_t)NH*3*NH];        // rounded W_qkv
__device__ float g_wor[(size_t)NH*NH];            // rounded W_o

// ---------------- helpers ----------------------------------------------------
__device__ __forceinline__ float tf32f(float x) {
    unsigned u; asm("cvt.rna.tf32.f32 %0, %1;" : "=r"(u) : "f"(x));
    return __uint_as_float(u);
}

__device__ __forceinline__ void mma8(float* d, const unsigned* a, const unsigned* b) {
    asm volatile(
        "mma.sync.aligned.m16n8k8.row.col.f32.tf32.tf32.f32 "
        "{%0,%1,%2,%3}, {%4,%5,%6,%7}, {%8,%9}, {%0,%1,%2,%3};\n"
        : "+f"(d[0]), "+f"(d[1]), "+f"(d[2]), "+f"(d[3])
        : "r"(a[0]), "r"(a[1]), "r"(a[2]), "r"(a[3]), "r"(b[0]), "r"(b[1]));
}

__device__ __forceinline__ void ldsm4(unsigned* r, unsigned addr) {
    asm volatile("ldmatrix.sync.aligned.m8n8.x4.shared.b16 {%0,%1,%2,%3}, [%4];"
        : "=r"(r[0]), "=r"(r[1]), "=r"(r[2]), "=r"(r[3]) : "r"(addr));
}

#define CP_ASYNC16(saddr, gptr) \
    asm volatile("cp.async.cg.shared.global [%0], [%1], 16;" :: "r"(saddr), "l"(gptr))
#define CP_COMMIT() asm volatile("cp.async.commit_group;" ::: "memory")
#define CP_WAIT1()  asm volatile("cp.async.wait_group 1;" ::: "memory")

__device__ __forceinline__ unsigned smem_u32(const void* p) {
    unsigned a;
    asm("{ .reg .u64 t; cvta.to.shared.u64 t, %1; cvt.u32.u64 %0, t; }" : "=r"(a) : "l"(p));
    return a;
}

// ---------------- pre-round: dst = tf32(src), vectorized ---------------------
__global__ void round_copy(const float* __restrict__ src, float* __restrict__ dst, int n4) {
    int stride = gridDim.x * blockDim.x;
    for (int i = blockIdx.x * blockDim.x + threadIdx.x; i < n4; i += stride) {
        float4 v = ((const float4*)src)[i];
        v.x = tf32f(v.x); v.y = tf32f(v.y); v.z = tf32f(v.z); v.w = tf32f(v.w);
        ((float4*)dst)[i] = v;
    }
}

__device__ __forceinline__ void scatter_qkv(int m, int n, float v) {
    int b = m >> 11, s = m & 2047;
    int which = n >> 12, rem = n & 4095;
    int h = rem >> 7, d = rem & 127;
    size_t idx = ((((size_t)b * NHEADS + h) * NS) + s) * HD + d;
    // Q pre-scaled + rounded; K/V rounded (flash consumes raw)
    if (which == 0)      g_q[idx] = tf32f(v * QSCALE);
    else if (which == 1) g_k[idx] = tf32f(v);
    else                 g_v[idx] = tf32f(v);
}

// =============================================================================
// GEMM: C[M,N] = A[M,K] @ W[K,N] + bias.  Operands PRE-ROUNDED to tf32.
// CTA 128x128, ktile 32, 128 threads = 4 warps, warp tile 64x64 (Mt=4, Nt=8).
// 3-stage cp.async pipeline (1 syncthreads per ktile).
// Smem/stage: A [128][36] (pad 4) + B [32][136] (pad 8) = 35840B; 3 stages.
// A-fragments: one ldmatrix.x4 each (conflict-free, row stride 144B).
// B-fragments: 2x LDS.32, bank = 8*lq + lr, conflict-free.
// MODE 0: A=g_xr, W=g_wqkvr, epilogue scatters rounded Q/K/V.
// MODE 1: A=g_ctx, W=g_wor,  epilogue writes C + bias (raw fp32).
// =============================================================================
#define STG_F 8960          // floats per stage
#define GEMM_SMEM (3 * STG_F * 4)

template<int MODE>
__global__ __launch_bounds__(128, 2) void gemm_tf32(
    const float* __restrict__ bias, float* __restrict__ C, int M, int N, int K)
{
    extern __shared__ float dsm[];
    const unsigned sbase = smem_u32(dsm);

    const int tid  = threadIdx.x;
    const int warp = tid >> 5, lane = tid & 31;
    const int wm = warp >> 1, wn = warp & 1;          // 2x2 warp grid
    const int lq = lane & 3, lr = lane >> 2;
    const int brow = blockIdx.y * 128, bcol = blockIdx.x * 128;

    const float* gA = ((MODE == 0) ? g_xr : g_ctx) + (size_t)brow * K;
    const float* gB = ((MODE == 0) ? g_wqkvr : g_wor) + bcol;

    // cp.async thread assignments
    const int aRow = tid >> 3, aC = tid & 7;          // A: 8 chunks/thread via +128
    const int bRow = tid >> 5, bC = tid & 31;         // B: 8 chunks/thread via +128

    const int ntiles = K >> 5;

    auto issue = [&](int kt) {
        if (kt < ntiles) {
            const int st = kt - (kt / 3) * 3;
            const unsigned sA = sbase + st * (STG_F * 4);
            const unsigned sB = sA + 4608 * 4;
            const float* ga = gA + kt * 32;
            #pragma unroll
            for (int i = 0; i < 8; i++) {
                int row = aRow + 16 * i;
                CP_ASYNC16(sA + (row * 36 + aC * 4) * 4, ga + (size_t)row * K + aC * 4);
            }
            const float* gb = gB + (size_t)kt * 32 * N;
            #pragma unroll
            for (int i = 0; i < 8; i++) {
                int row = bRow + 4 * i;
                CP_ASYNC16(sB + (row * 136 + bC * 4) * 4, gb + (size_t)row * N + bC * 4);
            }
        }
        CP_COMMIT();
    };

    float acc[4][8][4];
    #pragma unroll
    for (int mi = 0; mi < 4; mi++)
        #pragma unroll
        for (int ni = 0; ni < 8; ni++)
            #pragma unroll
            for (int j = 0; j < 4; j++) acc[mi][ni][j] = 0.f;

    issue(0); issue(1);

    // lane-constant piece of ldmatrix address (floats)
    const int aLdsmOff = (lane & 15) * 36 + ((lane >> 4) << 2);

    for (int kt = 0; kt < ntiles; kt++) {
        CP_WAIT1();
        __syncthreads();
        const int st = kt - (kt / 3) * 3;
        const unsigned aBase = sbase + st * (STG_F * 4);
        const float* sB = dsm + st * STG_F + 4608;

        #pragma unroll
        for (int ks = 0; ks < 4; ks++) {
            unsigned af[4][4];
            #pragma unroll
            for (int mi = 0; mi < 4; mi++)
                ldsm4(af[mi], aBase + ((wm * 64 + mi * 16) * 36 + ks * 8 + aLdsmOff) * 4);
            float bf[8][2];
            const float* bp = sB + (ks * 8 + lq) * 136 + wn * 64 + lr;
            #pragma unroll
            for (int ni = 0; ni < 8; ni++) {
                bf[ni][0] = bp[ni * 8];
                bf[ni][1] = bp[ni * 8 + 4 * 136];
            }
            #pragma unroll
            for (int ni = 0; ni < 8; ni++)
                #pragma unroll
                for (int mi = 0; mi < 4; mi++)
                    mma8(acc[mi][ni], af[mi], (const unsigned*)bf[ni]);
        }
        issue(kt + 2);
    }

    // epilogue
    #pragma unroll
    for (int mi = 0; mi < 4; mi++) {
        int r0 = brow + wm * 64 + mi * 16 + lr;
        #pragma unroll
        for (int ni = 0; ni < 8; ni++) {
            int c0 = bcol + wn * 64 + ni * 8 + 2 * lq;
            float v0 = acc[mi][ni][0] + bias[c0];
            float v1 = acc[mi][ni][1] + bias[c0 + 1];
            float v2 = acc[mi][ni][2] + bias[c0];
            float v3 = acc[mi][ni][3] + bias[c0 + 1];
            if (MODE == 0) {
                scatter_qkv(r0,     c0,     v0);
                scatter_qkv(r0,     c0 + 1, v1);
                scatter_qkv(r0 + 8, c0,     v2);
                scatter_qkv(r0 + 8, c0 + 1, v3);
            } else {
                C[(size_t)r0 * N + c0]           = v0;
                C[(size_t)r0 * N + c0 + 1]       = v1;
                C[(size_t)(r0 + 8) * N + c0]     = v2;
                C[(size_t)(r0 + 8) * N + c0 + 1] = v3;
            }
        }
    }
}

// ---------------- flash attention (structure of the 5602us version) ----------
// grid (S/64, B*HEADS), 128 threads = 4 warps; warp owns 16 q-rows.
// Q/K/V arrive pre-rounded (Q pre-scaled); only P needs tf32 rounding.
#define QS_STRIDE 132
#define KS_STRIDE 132
#define VS_STRIDE 136
#define PS_STRIDE 68
#define SM_K_OFF  (64 * QS_STRIDE)
#define SM_V_OFF  (SM_K_OFF + 64 * KS_STRIDE)
#define SM_P_OFF  (SM_V_OFF + 64 * VS_STRIDE)
#define SMEM_FLASH ((SM_P_OFF + 64 * PS_STRIDE) * 4)

__global__ __launch_bounds__(128, 1) void flash_attn()
{
    extern __shared__ float sm[];
    float* Qs = sm;
    float* Ks = sm + SM_K_OFF;
    float* Vs = sm + SM_V_OFF;
    float* Ps = sm + SM_P_OFF;

    const int tid = threadIdx.x, warp = tid >> 5, lane = tid & 31;
    const int lq = lane & 3, lr = lane >> 2;
    const int bh = blockIdx.y, qt = blockIdx.x;

    const float* Qg = g_q + ((size_t)bh * NS + qt * 64) * HD;
    const float* Kg = g_k + (size_t)bh * NS * HD;
    const float* Vg = g_v + (size_t)bh * NS * HD;

    // load Q tile (already scaled + rounded)
    #pragma unroll
    for (int i = 0; i < 16; i++) {
        int f = tid + i * 128;
        int row = f >> 5, c4 = (f & 31) << 2;
        float4 v = *(const float4*)(Qg + (size_t)row * HD + c4);
        Qs[row * QS_STRIDE + c4 + 0] = v.x;
        Qs[row * QS_STRIDE + c4 + 1] = v.y;
        Qs[row * QS_STRIDE + c4 + 2] = v.z;
        Qs[row * QS_STRIDE + c4 + 3] = v.w;
    }

    float oacc[16][4];
    #pragma unroll
    for (int ni = 0; ni < 16; ni++)
        #pragma unroll
        for (int j = 0; j < 4; j++) oacc[ni][j] = 0.f;

    float m0 = -CUDART_INF_F, m1 = -CUDART_INF_F, l0 = 0.f, l1 = 0.f;
    const int r = warp * 16 + lr;

    for (int kt = 0; kt < NS / 64; kt++) {
        __syncthreads();   // prior PV done before overwriting K/V
        #pragma unroll
        for (int i = 0; i < 16; i++) {
            int f = tid + i * 128;
            int row = f >> 5, c4 = (f & 31) << 2;
            float4 kv = *(const float4*)(Kg + (size_t)(kt * 64 + row) * HD + c4);
            Ks[row * KS_STRIDE + c4 + 0] = kv.x;
            Ks[row * KS_STRIDE + c4 + 1] = kv.y;
            Ks[row * KS_STRIDE + c4 + 2] = kv.z;
            Ks[row * KS_STRIDE + c4 + 3] = kv.w;
            float4 vv = *(const float4*)(Vg + (size_t)(kt * 64 + row) * HD + c4);
            Vs[row * VS_STRIDE + c4 + 0] = vv.x;
            Vs[row * VS_STRIDE + c4 + 1] = vv.y;
            Vs[row * VS_STRIDE + c4 + 2] = vv.z;
            Vs[row * VS_STRIDE + c4 + 3] = vv.w;
        }
        __syncthreads();

        // S = Q K^T  (warp: 16 rows x 64 kv-cols)
        float sacc[8][4];
        #pragma unroll
        for (int ni = 0; ni < 8; ni++)
            #pragma unroll
            for (int j = 0; j < 4; j++) sacc[ni][j] = 0.f;

        #pragma unroll
        for (int ks = 0; ks < 16; ks++) {
            int k = ks * 8;
            unsigned qa[4];
            qa[0] = __float_as_uint(Qs[r * QS_STRIDE + k + lq]);
            qa[1] = __float_as_uint(Qs[(r + 8) * QS_STRIDE + k + lq]);
            qa[2] = __float_as_uint(Qs[r * QS_STRIDE + k + lq + 4]);
            qa[3] = __float_as_uint(Qs[(r + 8) * QS_STRIDE + k + lq + 4]);
            #pragma unroll
            for (int ni = 0; ni < 8; ni++) {
                int j = ni * 8 + lr;
                unsigned kb[2];
                kb[0] = __float_as_uint(Ks[j * KS_STRIDE + k + lq]);
                kb[1] = __float_as_uint(Ks[j * KS_STRIDE + k + lq + 4]);
                mma8(sacc[ni], qa, kb);
            }
        }

        // online softmax
        float mt0 = -CUDART_INF_F, mt1 = -CUDART_INF_F;
        #pragma unroll
        for (int ni = 0; ni < 8; ni++) {
            mt0 = fmaxf(mt0, fmaxf(sacc[ni][0], sacc[ni][1]));
            mt1 = fmaxf(mt1, fmaxf(sacc[ni][2], sacc[ni][3]));
        }
        mt0 = fmaxf(mt0, __shfl_xor_sync(0xffffffffu, mt0, 1));
        mt0 = fmaxf(mt0, __shfl_xor_sync(0xffffffffu, mt0, 2));
        mt1 = fmaxf(mt1, __shfl_xor_sync(0xffffffffu, mt1, 1));
        mt1 = fmaxf(mt1, __shfl_xor_sync(0xffffffffu, mt1, 2));

        float mn0 = fmaxf(m0, mt0), mn1 = fmaxf(m1, mt1);
        float a0 = __expf(m0 - mn0), a1 = __expf(m1 - mn1);

        float sum0 = 0.f, sum1 = 0.f;
        #pragma unroll
        for (int ni = 0; ni < 8; ni++) {
            int c = ni * 8 + 2 * lq;
            float p0 = __expf(sacc[ni][0] - mn0);
            float p1 = __expf(sacc[ni][1] - mn0);
            float p2 = __expf(sacc[ni][2] - mn1);
            float p3 = __expf(sacc[ni][3] - mn1);
            sum0 += p0 + p1;  sum1 += p2 + p3;
            Ps[r * PS_STRIDE + c]           = tf32f(p0);
            Ps[r * PS_STRIDE + c + 1]       = tf32f(p1);
            Ps[(r + 8) * PS_STRIDE + c]     = tf32f(p2);
            Ps[(r + 8) * PS_STRIDE + c + 1] = tf32f(p3);
        }
        sum0 += __shfl_xor_sync(0xffffffffu, sum0, 1);
        sum0 += __shfl_xor_sync(0xffffffffu, sum0, 2);
        sum1 += __shfl_xor_sync(0xffffffffu, sum1, 1);
        sum1 += __shfl_xor_sync(0xffffffffu, sum1, 2);

        l0 = l0 * a0 + sum0;
        l1 = l1 * a1 + sum1;
        m0 = mn0; m1 = mn1;

        #pragma unroll
        for (int ni = 0; ni < 16; ni++) {
            oacc[ni][0] *= a0; oacc[ni][1] *= a0;
            oacc[ni][2] *= a1; oacc[ni][3] *= a1;
        }
        __syncwarp();  // order P smem writes before same-warp frag reads

        // O += P V
        #pragma unroll
        for (int ks = 0; ks < 8; ks++) {
            int k = ks * 8;
            unsigned pa[4];
            pa[0] = __float_as_uint(Ps[r * PS_STRIDE + k + lq]);
            pa[1] = __float_as_uint(Ps[(r + 8) * PS_STRIDE + k + lq]);
            pa[2] = __float_as_uint(Ps[r * PS_STRIDE + k + lq + 4]);
            pa[3] = __float_as_uint(Ps[(r + 8) * PS_STRIDE + k + lq + 4]);
            #pragma unroll
            for (int ni = 0; ni < 16; ni++) {
                int n = ni * 8 + lr;
                unsigned vb[2];
                vb[0] = __float_as_uint(Vs[(k + lq) * VS_STRIDE + n]);
                vb[1] = __float_as_uint(Vs[(k + lq + 4) * VS_STRIDE + n]);
                mma8(oacc[ni], pa, vb);
            }
        }
    }

    // epilogue: normalize, round (next GEMM consumes raw), write token-major
    float inv0 = 1.f / l0, inv1 = 1.f / l1;
    int b = bh >> 5, h = bh & 31;
    int row0 = qt * 64 + r;
    size_t tok0 = ((size_t)b * NS + row0) * NH;
    size_t tok1 = ((size_t)b * NS + row0 + 8) * NH;
    #pragma unroll
    for (int ni = 0; ni < 16; ni++) {
        int col = h * HD + ni * 8 + 2 * lq;
        g_ctx[tok0 + col]     = tf32f(oacc[ni][0] * inv0);
        g_ctx[tok0 + col + 1] = tf32f(oacc[ni][1] * inv0);
        g_ctx[tok1 + col]     = tf32f(oacc[ni][2] * inv1);
        g_ctx[tok1 + col + 1] = tf32f(oacc[ni][3] * inv1);
    }
}

// ---------------- launch ------------------------------------------------------
extern "C" void kernel_launch(void* const* d_in, const int* in_sizes, int n_in,
                              void* d_out, int out_size)
{
    const float* x    = (const float*)d_in[0];
    const float* wqkv = (const float*)d_in[1];
    const float* bqkv = (const float*)d_in[2];
    const float* wo   = (const float*)d_in[3];
    const float* bo   = (const float*)d_in[4];
    float* out = (float*)d_out;

    cudaFuncSetAttribute(gemm_tf32<0>, cudaFuncAttributeMaxDynamicSharedMemorySize, GEMM_SMEM);
    cudaFuncSetAttribute(gemm_tf32<1>, cudaFuncAttributeMaxDynamicSharedMemorySize, GEMM_SMEM);
    cudaFuncSetAttribute(flash_attn,   cudaFuncAttributeMaxDynamicSharedMemorySize, SMEM_FLASH);

    float* xr; float* wqkvr; float* wor;
    cudaGetSymbolAddress((void**)&xr,    g_xr);
    cudaGetSymbolAddress((void**)&wqkvr, g_wqkvr);
    cudaGetSymbolAddress((void**)&wor,   g_wor);

    // 0) pre-round all GEMM operands to tf32 (removes cvt from hot loops)
    round_copy<<<1024, 256>>>(x,    xr,    NTOK * NH / 4);
    round_copy<<<2048, 256>>>(wqkv, wqkvr, NH * 3 * NH / 4);
    round_copy<<<1024, 256>>>(wo,   wor,   NH * NH / 4);

    // 1) QKV GEMM + bias -> rounded (Q pre-scaled) Q/K/V in [b][h][s][d]
    gemm_tf32<0><<<dim3(3 * NH / 128, NTOK / 128), 128, GEMM_SMEM>>>(
        bqkv, nullptr, NTOK, 3 * NH, NH);

    // 2) flash attention -> rounded ctx (token-major)
    flash_attn<<<dim3(NS / 64, NB * NHEADS), 128, SMEM_FLASH>>>();

    // 3) output projection + bias -> final fp32 out
    gemm_tf32<1><<<dim3(NH / 128, NTOK / 128), 128, GEMM_SMEM>>>(
        bo, out, NTOK, NH, NH);
}

// round 7
// speedup vs baseline: 2.2252x; 1.1292x over previous
#include <cuda_runtime.h>
#include <cstdint>
#include <math_constants.h>

#define NHEADS 32
#define HD     128
#define NB     2
#define NS     2048
#define NH     4096
#define NTOK   (NB*NS)   // 4096 tokens
#define QSCALE 0.08838834764831845f   // 1/sqrt(128)

// ---------------- scratch (device globals: no allocations allowed) ----------
__device__ float g_q[(size_t)NB*NHEADS*NS*HD];    // [b][h][s][d]  (pre-scaled+rounded)
__device__ float g_k[(size_t)NB*NHEADS*NS*HD];    // rounded
__device__ float g_v[(size_t)NB*NHEADS*NS*HD];    // rounded
__device__ float g_ctx[(size_t)NTOK*NH];          // token-major, rounded
__device__ float g_xr[(size_t)NTOK*NH];           // rounded x
__device__ float g_wqkvr[(size_t)NH*3*NH];        // rounded W_qkv
__device__ float g_wor[(size_t)NH*NH];            // rounded W_o

// ---------------- helpers ----------------------------------------------------
__device__ __forceinline__ float tf32f(float x) {
    unsigned u; asm("cvt.rna.tf32.f32 %0, %1;" : "=r"(u) : "f"(x));
    return __uint_as_float(u);
}

__device__ __forceinline__ void mma8(float* d, const unsigned* a, const unsigned* b) {
    asm volatile(
        "mma.sync.aligned.m16n8k8.row.col.f32.tf32.tf32.f32 "
        "{%0,%1,%2,%3}, {%4,%5,%6,%7}, {%8,%9}, {%0,%1,%2,%3};\n"
        : "+f"(d[0]), "+f"(d[1]), "+f"(d[2]), "+f"(d[3])
        : "r"(a[0]), "r"(a[1]), "r"(a[2]), "r"(a[3]), "r"(b[0]), "r"(b[1]));
}

__device__ __forceinline__ void ldsm4(unsigned* r, unsigned addr) {
    asm volatile("ldmatrix.sync.aligned.m8n8.x4.shared.b16 {%0,%1,%2,%3}, [%4];"
        : "=r"(r[0]), "=r"(r[1]), "=r"(r[2]), "=r"(r[3]) : "r"(addr));
}

#define CP_ASYNC16(saddr, gptr) \
    asm volatile("cp.async.cg.shared.global [%0], [%1], 16;" :: "r"(saddr), "l"(gptr))
#define CP_COMMIT() asm volatile("cp.async.commit_group;" ::: "memory")
#define CP_WAIT1()  asm volatile("cp.async.wait_group 1;" ::: "memory")

__device__ __forceinline__ unsigned smem_u32(const void* p) {
    unsigned a;
    asm("{ .reg .u64 t; cvta.to.shared.u64 t, %1; cvt.u32.u64 %0, t; }" : "=r"(a) : "l"(p));
    return a;
}

// ---------------- pre-round: dst = tf32(src), vectorized ---------------------
__global__ void round_copy(const float* __restrict__ src, float* __restrict__ dst, int n4) {
    int stride = gridDim.x * blockDim.x;
    for (int i = blockIdx.x * blockDim.x + threadIdx.x; i < n4; i += stride) {
        float4 v = ((const float4*)src)[i];
        v.x = tf32f(v.x); v.y = tf32f(v.y); v.z = tf32f(v.z); v.w = tf32f(v.w);
        ((float4*)dst)[i] = v;
    }
}

__device__ __forceinline__ void scatter_qkv(int m, int n, float v) {
    int b = m >> 11, s = m & 2047;
    int which = n >> 12, rem = n & 4095;
    int h = rem >> 7, d = rem & 127;
    size_t idx = ((((size_t)b * NHEADS + h) * NS) + s) * HD + d;
    if (which == 0)      g_q[idx] = tf32f(v * QSCALE);
    else if (which == 1) g_k[idx] = tf32f(v);
    else                 g_v[idx] = tf32f(v);
}

// =============================================================================
// GEMM (unchanged from round 6): CTA 128x128, ktile 32, 128 thr, 3-stage cp.async
// =============================================================================
#define STG_F 8960          // floats per stage
#define GEMM_SMEM (3 * STG_F * 4)

template<int MODE>
__global__ __launch_bounds__(128, 2) void gemm_tf32(
    const float* __restrict__ bias, float* __restrict__ C, int M, int N, int K)
{
    extern __shared__ float dsm[];
    const unsigned sbase = smem_u32(dsm);

    const int tid  = threadIdx.x;
    const int warp = tid >> 5, lane = tid & 31;
    const int wm = warp >> 1, wn = warp & 1;
    const int lq = lane & 3, lr = lane >> 2;
    const int brow = blockIdx.y * 128, bcol = blockIdx.x * 128;

    const float* gA = ((MODE == 0) ? g_xr : g_ctx) + (size_t)brow * K;
    const float* gB = ((MODE == 0) ? g_wqkvr : g_wor) + bcol;

    const int aRow = tid >> 3, aC = tid & 7;
    const int bRow = tid >> 5, bC = tid & 31;

    const int ntiles = K >> 5;

    auto issue = [&](int kt) {
        if (kt < ntiles) {
            const int st = kt - (kt / 3) * 3;
            const unsigned sA = sbase + st * (STG_F * 4);
            const unsigned sB = sA + 4608 * 4;
            const float* ga = gA + kt * 32;
            #pragma unroll
            for (int i = 0; i < 8; i++) {
                int row = aRow + 16 * i;
                CP_ASYNC16(sA + (row * 36 + aC * 4) * 4, ga + (size_t)row * K + aC * 4);
            }
            const float* gb = gB + (size_t)kt * 32 * N;
            #pragma unroll
            for (int i = 0; i < 8; i++) {
                int row = bRow + 4 * i;
                CP_ASYNC16(sB + (row * 136 + bC * 4) * 4, gb + (size_t)row * N + bC * 4);
            }
        }
        CP_COMMIT();
    };

    float acc[4][8][4];
    #pragma unroll
    for (int mi = 0; mi < 4; mi++)
        #pragma unroll
        for (int ni = 0; ni < 8; ni++)
            #pragma unroll
            for (int j = 0; j < 4; j++) acc[mi][ni][j] = 0.f;

    issue(0); issue(1);

    const int aLdsmOff = (lane & 15) * 36 + ((lane >> 4) << 2);

    for (int kt = 0; kt < ntiles; kt++) {
        CP_WAIT1();
        __syncthreads();
        const int st = kt - (kt / 3) * 3;
        const unsigned aBase = sbase + st * (STG_F * 4);
        const float* sB = dsm + st * STG_F + 4608;

        #pragma unroll
        for (int ks = 0; ks < 4; ks++) {
            unsigned af[4][4];
            #pragma unroll
            for (int mi = 0; mi < 4; mi++)
                ldsm4(af[mi], aBase + ((wm * 64 + mi * 16) * 36 + ks * 8 + aLdsmOff) * 4);
            float bf[8][2];
            const float* bp = sB + (ks * 8 + lq) * 136 + wn * 64 + lr;
            #pragma unroll
            for (int ni = 0; ni < 8; ni++) {
                bf[ni][0] = bp[ni * 8];
                bf[ni][1] = bp[ni * 8 + 4 * 136];
            }
            #pragma unroll
            for (int ni = 0; ni < 8; ni++)
                #pragma unroll
                for (int mi = 0; mi < 4; mi++)
                    mma8(acc[mi][ni], af[mi], (const unsigned*)bf[ni]);
        }
        issue(kt + 2);
    }

    #pragma unroll
    for (int mi = 0; mi < 4; mi++) {
        int r0 = brow + wm * 64 + mi * 16 + lr;
        #pragma unroll
        for (int ni = 0; ni < 8; ni++) {
            int c0 = bcol + wn * 64 + ni * 8 + 2 * lq;
            float v0 = acc[mi][ni][0] + bias[c0];
            float v1 = acc[mi][ni][1] + bias[c0 + 1];
            float v2 = acc[mi][ni][2] + bias[c0];
            float v3 = acc[mi][ni][3] + bias[c0 + 1];
            if (MODE == 0) {
                scatter_qkv(r0,     c0,     v0);
                scatter_qkv(r0,     c0 + 1, v1);
                scatter_qkv(r0 + 8, c0,     v2);
                scatter_qkv(r0 + 8, c0 + 1, v3);
            } else {
                C[(size_t)r0 * N + c0]           = v0;
                C[(size_t)r0 * N + c0 + 1]       = v1;
                C[(size_t)(r0 + 8) * N + c0]     = v2;
                C[(size_t)(r0 + 8) * N + c0 + 1] = v3;
            }
        }
    }
}

// =============================================================================
// Flash attention v3: CTA = 256 q-rows, 256 threads = 8 warps, warp = 32 rows
// (2 m16 tiles). KV tile 64. P lives in REGISTERS (quad-shuffle from S C-frag
// to PV A-frag). Q a-frags via ldmatrix.x4 (stride 132 -> conflict-free).
// K b-frags: bank 4*lr+lq (cf). V b-frags: bank 8*lq+lr (cf).
// Smem: Q 256x132 + K 64x132 + V 64x136 = 203,776 B. 1 CTA/SM.
// =============================================================================
#define FQ_STRIDE 132
#define FK_STRIDE 132
#define FV_STRIDE 136
#define SM_FK (256 * FQ_STRIDE)
#define SM_FV (SM_FK + 64 * FK_STRIDE)
#define SMEM_FLASH ((SM_FV + 64 * FV_STRIDE) * 4)

__global__ __launch_bounds__(256, 1) void flash_attn()
{
    extern __shared__ float sm[];
    float* Qs = sm;
    float* Ks = sm + SM_FK;
    float* Vs = sm + SM_FV;
    const unsigned qbase = smem_u32(sm);

    const int tid = threadIdx.x, w = tid >> 5, lane = tid & 31;
    const int lq = lane & 3, lr = lane >> 2;
    const int bh = blockIdx.y, qt = blockIdx.x;

    const float* Qg = g_q + ((size_t)bh * NS + qt * 256) * HD;
    const float* Kg = g_k + (size_t)bh * NS * HD;
    const float* Vg = g_v + (size_t)bh * NS * HD;

    // ---- load Q tile 256x128 (already scaled+rounded) -----------------------
    #pragma unroll
    for (int i = 0; i < 32; i++) {
        int f = tid + i * 256;
        int row = f >> 5, c4 = (f & 31) << 2;
        *(float4*)(Qs + row * FQ_STRIDE + c4) = *(const float4*)(Qg + (size_t)row * HD + c4);
    }

    float oacc[2][16][4];
    #pragma unroll
    for (int mi = 0; mi < 2; mi++)
        #pragma unroll
        for (int nt = 0; nt < 16; nt++)
            #pragma unroll
            for (int j = 0; j < 4; j++) oacc[mi][nt][j] = 0.f;

    float mrow[2][2], lrow[2][2];
    #pragma unroll
    for (int mi = 0; mi < 2; mi++) {
        mrow[mi][0] = -CUDART_INF_F; mrow[mi][1] = -CUDART_INF_F;
        lrow[mi][0] = 0.f;           lrow[mi][1] = 0.f;
    }

    // ldmatrix lane-constant offset for this warp's 32 rows
    const int aOff0 = (w * 32 + (lane & 15)) * FQ_STRIDE + ((lane >> 4) << 2);
    const int psrc0 = (lane & ~3) | (lq >> 1);
    const int psrc1 = psrc0 + 2;
    const bool podd = (lq & 1);

    for (int kt = 0; kt < NS / 64; kt++) {
        __syncthreads();   // prior PV reads done before overwriting K/V
        #pragma unroll
        for (int i = 0; i < 8; i++) {
            int f = tid + i * 256;
            int row = f >> 5, c4 = (f & 31) << 2;
            *(float4*)(Ks + row * FK_STRIDE + c4) =
                *(const float4*)(Kg + (size_t)(kt * 64 + row) * HD + c4);
            *(float4*)(Vs + row * FV_STRIDE + c4) =
                *(const float4*)(Vg + (size_t)(kt * 64 + row) * HD + c4);
        }
        __syncthreads();

        // ---- S = Q K^T : warp = 32 q-rows x 64 kv, k = 128 ------------------
        float sacc[2][8][4];
        #pragma unroll
        for (int mi = 0; mi < 2; mi++)
            #pragma unroll
            for (int ni = 0; ni < 8; ni++)
                #pragma unroll
                for (int j = 0; j < 4; j++) sacc[mi][ni][j] = 0.f;

        #pragma unroll
        for (int ks = 0; ks < 16; ks++) {
            unsigned af[2][4];
            ldsm4(af[0], qbase + (aOff0 + ks * 8) * 4);
            ldsm4(af[1], qbase + (aOff0 + 16 * FQ_STRIDE + ks * 8) * 4);
            const float* kp = Ks + lr * FK_STRIDE + ks * 8 + lq;
            #pragma unroll
            for (int ni = 0; ni < 8; ni++) {
                unsigned kb[2];
                kb[0] = __float_as_uint(kp[ni * 8 * FK_STRIDE]);
                kb[1] = __float_as_uint(kp[ni * 8 * FK_STRIDE + 4]);
                mma8(sacc[0][ni], af[0], kb);
                mma8(sacc[1][ni], af[1], kb);
            }
        }

        // ---- online softmax (4 row-groups: mi x {lr, lr+8}) -----------------
        #pragma unroll
        for (int mi = 0; mi < 2; mi++) {
            float mt0 = -CUDART_INF_F, mt1 = -CUDART_INF_F;
            #pragma unroll
            for (int ni = 0; ni < 8; ni++) {
                mt0 = fmaxf(mt0, fmaxf(sacc[mi][ni][0], sacc[mi][ni][1]));
                mt1 = fmaxf(mt1, fmaxf(sacc[mi][ni][2], sacc[mi][ni][3]));
            }
            mt0 = fmaxf(mt0, __shfl_xor_sync(0xffffffffu, mt0, 1));
            mt0 = fmaxf(mt0, __shfl_xor_sync(0xffffffffu, mt0, 2));
            mt1 = fmaxf(mt1, __shfl_xor_sync(0xffffffffu, mt1, 1));
            mt1 = fmaxf(mt1, __shfl_xor_sync(0xffffffffu, mt1, 2));

            float mn0 = fmaxf(mrow[mi][0], mt0), mn1 = fmaxf(mrow[mi][1], mt1);
            float a0 = __expf(mrow[mi][0] - mn0), a1 = __expf(mrow[mi][1] - mn1);

            float sum0 = 0.f, sum1 = 0.f;
            #pragma unroll
            for (int ni = 0; ni < 8; ni++) {
                sacc[mi][ni][0] = __expf(sacc[mi][ni][0] - mn0);
                sacc[mi][ni][1] = __expf(sacc[mi][ni][1] - mn0);
                sacc[mi][ni][2] = __expf(sacc[mi][ni][2] - mn1);
                sacc[mi][ni][3] = __expf(sacc[mi][ni][3] - mn1);
                sum0 += sacc[mi][ni][0] + sacc[mi][ni][1];
                sum1 += sacc[mi][ni][2] + sacc[mi][ni][3];
            }
            sum0 += __shfl_xor_sync(0xffffffffu, sum0, 1);
            sum0 += __shfl_xor_sync(0xffffffffu, sum0, 2);
            sum1 += __shfl_xor_sync(0xffffffffu, sum1, 1);
            sum1 += __shfl_xor_sync(0xffffffffu, sum1, 2);

            lrow[mi][0] = lrow[mi][0] * a0 + sum0;
            lrow[mi][1] = lrow[mi][1] * a1 + sum1;
            mrow[mi][0] = mn0; mrow[mi][1] = mn1;

            #pragma unroll
            for (int nt = 0; nt < 16; nt++) {
                oacc[mi][nt][0] *= a0; oacc[mi][nt][1] *= a0;
                oacc[mi][nt][2] *= a1; oacc[mi][nt][3] *= a1;
            }
        }

        // ---- O += P V : P from registers via quad shuffle -------------------
        #pragma unroll
        for (int ks = 0; ks < 8; ks++) {
            unsigned pa[2][4];
            #pragma unroll
            for (int mi = 0; mi < 2; mi++) {
                float y0 = __shfl_sync(0xffffffffu, sacc[mi][ks][0], psrc0);
                float y1 = __shfl_sync(0xffffffffu, sacc[mi][ks][1], psrc0);
                float y2 = __shfl_sync(0xffffffffu, sacc[mi][ks][2], psrc0);
                float y3 = __shfl_sync(0xffffffffu, sacc[mi][ks][3], psrc0);
                float z0 = __shfl_sync(0xffffffffu, sacc[mi][ks][0], psrc1);
                float z1 = __shfl_sync(0xffffffffu, sacc[mi][ks][1], psrc1);
                float z2 = __shfl_sync(0xffffffffu, sacc[mi][ks][2], psrc1);
                float z3 = __shfl_sync(0xffffffffu, sacc[mi][ks][3], psrc1);
                pa[mi][0] = __float_as_uint(tf32f(podd ? y1 : y0));
                pa[mi][1] = __float_as_uint(tf32f(podd ? y3 : y2));
                pa[mi][2] = __float_as_uint(tf32f(podd ? z1 : z0));
                pa[mi][3] = __float_as_uint(tf32f(podd ? z3 : z2));
            }
            const float* vp = Vs + (ks * 8 + lq) * FV_STRIDE + lr;
            #pragma unroll
            for (int nt = 0; nt < 16; nt++) {
                unsigned vb[2];
                vb[0] = __float_as_uint(vp[nt * 8]);
                vb[1] = __float_as_uint(vp[nt * 8 + 4 * FV_STRIDE]);
                mma8(oacc[0][nt], pa[0], vb);
                mma8(oacc[1][nt], pa[1], vb);
            }
        }
    }

    // ---- epilogue: normalize, round, write ctx token-major ------------------
    int b = bh >> 5, h = bh & 31;
    #pragma unroll
    for (int mi = 0; mi < 2; mi++) {
        float inv0 = 1.f / lrow[mi][0], inv1 = 1.f / lrow[mi][1];
        int r0 = qt * 256 + w * 32 + mi * 16 + lr;
        size_t tok0 = ((size_t)b * NS + r0) * NH;
        size_t tok1 = ((size_t)b * NS + r0 + 8) * NH;
        #pragma unroll
        for (int nt = 0; nt < 16; nt++) {
            int col = h * HD + nt * 8 + 2 * lq;
            g_ctx[tok0 + col]     = tf32f(oacc[mi][nt][0] * inv0);
            g_ctx[tok0 + col + 1] = tf32f(oacc[mi][nt][1] * inv0);
            g_ctx[tok1 + col]     = tf32f(oacc[mi][nt][2] * inv1);
            g_ctx[tok1 + col + 1] = tf32f(oacc[mi][nt][3] * inv1);
        }
    }
}

// ---------------- launch ------------------------------------------------------
extern "C" void kernel_launch(void* const* d_in, const int* in_sizes, int n_in,
                              void* d_out, int out_size)
{
    const float* x    = (const float*)d_in[0];
    const float* wqkv = (const float*)d_in[1];
    const float* bqkv = (const float*)d_in[2];
    const float* wo   = (const float*)d_in[3];
    const float* bo   = (const float*)d_in[4];
    float* out = (float*)d_out;

    cudaFuncSetAttribute(gemm_tf32<0>, cudaFuncAttributeMaxDynamicSharedMemorySize, GEMM_SMEM);
    cudaFuncSetAttribute(gemm_tf32<1>, cudaFuncAttributeMaxDynamicSharedMemorySize, GEMM_SMEM);
    cudaFuncSetAttribute(flash_attn,   cudaFuncAttributeMaxDynamicSharedMemorySize, SMEM_FLASH);

    float* xr; float* wqkvr; float* wor;
    cudaGetSymbolAddress((void**)&xr,    g_xr);
    cudaGetSymbolAddress((void**)&wqkvr, g_wqkvr);
    cudaGetSymbolAddress((void**)&wor,   g_wor);

    // 0) pre-round all GEMM operands to tf32
    round_copy<<<1024, 256>>>(x,    xr,    NTOK * NH / 4);
    round_copy<<<2048, 256>>>(wqkv, wqkvr, NH * 3 * NH / 4);
    round_copy<<<1024, 256>>>(wo,   wor,   NH * NH / 4);

    // 1) QKV GEMM + bias -> rounded (Q pre-scaled) Q/K/V in [b][h][s][d]
    gemm_tf32<0><<<dim3(3 * NH / 128, NTOK / 128), 128, GEMM_SMEM>>>(
        bqkv, nullptr, NTOK, 3 * NH, NH);

    // 2) flash attention -> rounded ctx (token-major)
    flash_attn<<<dim3(NS / 256, NB * NHEADS), 256, SMEM_FLASH>>>();

    // 3) output projection + bias -> final fp32 out
    gemm_tf32<1><<<dim3(NH / 128, NTOK / 128), 128, GEMM_SMEM>>>(
        bo, out, NTOK, NH, NH);
}